// round 9
// baseline (speedup 1.0000x reference)
#include <cuda_runtime.h>

// Row-normalize: out[b,i,j] = adj[b,i,j] / sum_j adj[b,i,j]  (nan/inf inv -> 0)
// Two tensors of [16, 1024, 1024] fp32; output = concat(out0, out1).
//
// Warp-per-row, 2-stage software pipeline within the row:
//   issue loads for half0 + half1 (half1 stays in flight),
//   reduce needs both halves -> but stores of half0 are issued while the
//   reduction result is broadcast, interleaving read/write streams at 2KB
//   granularity to soften DRAM bus turnaround bursts.
// Shuffle-only reduction, no smem, no block barriers.

constexpr int N       = 1024;
constexpr int THREADS = 512;            // 16 warps = 16 rows per CTA
constexpr int WARPS   = THREADS / 32;
constexpr int HALF    = 4;              // float4 per thread per half-row

__global__ __launch_bounds__(THREADS)
void row_norm_kernel(const float* __restrict__ in0,
                     const float* __restrict__ in1,
                     float* __restrict__ out,
                     int rows_per_tensor)   // 16384
{
    const int lane = threadIdx.x & 31;
    const int wid  = threadIdx.x >> 5;

    const long long row = (long long)blockIdx.x * WARPS + wid;
    const bool second = row >= rows_per_tensor;
    const float* __restrict__ src = second ? in1 : in0;
    const long long local_row = second ? (row - rows_per_tensor) : row;

    const float4* __restrict__ s =
        reinterpret_cast<const float4*>(src) + local_row * (N / 4) + lane;
    float4* __restrict__ d =
        reinterpret_cast<float4*>(out) + row * (N / 4) + lane;

    // Stage A: first half loads
    float4 a[HALF];
    #pragma unroll
    for (int i = 0; i < HALF; ++i) a[i] = __ldcs(s + i * 32);

    // Stage B: second half loads (independent, stay in flight)
    float4 b[HALF];
    #pragma unroll
    for (int i = 0; i < HALF; ++i) b[i] = __ldcs(s + (HALF + i) * 32);

    // Reduce half0 first (only waits on a[])
    float p = 0.0f;
    #pragma unroll
    for (int i = 0; i < HALF; ++i)
        p += ((a[i].x + a[i].y) + (a[i].z + a[i].w));
    // then half1
    #pragma unroll
    for (int i = 0; i < HALF; ++i)
        p += ((b[i].x + b[i].y) + (b[i].z + b[i].w));

    #pragma unroll
    for (int off = 16; off > 0; off >>= 1)
        p += __shfl_xor_sync(0xFFFFFFFFu, p, off);

    float inv = 1.0f / p;
    if (!isfinite(inv)) inv = 0.0f;

    // Store half0 immediately, then half1 — write bursts split in two.
    #pragma unroll
    for (int i = 0; i < HALF; ++i) {
        a[i].x *= inv; a[i].y *= inv; a[i].z *= inv; a[i].w *= inv;
        __stcs(d + i * 32, a[i]);
    }
    #pragma unroll
    for (int i = 0; i < HALF; ++i) {
        b[i].x *= inv; b[i].y *= inv; b[i].z *= inv; b[i].w *= inv;
        __stcs(d + (HALF + i) * 32, b[i]);
    }
}

extern "C" void kernel_launch(void* const* d_in, const int* in_sizes, int n_in,
                              void* d_out, int out_size)
{
    const float* adj0 = (const float*)d_in[0];
    const float* adj1 = (const float*)d_in[1];
    float* out = (float*)d_out;

    const int rows_per_tensor = in_sizes[0] / N;          // 16384
    const int total_rows = 2 * rows_per_tensor;           // 32768
    const int grid = total_rows / WARPS;                  // 2048

    row_norm_kernel<<<grid, THREADS>>>(adj0, adj1, out, rows_per_tensor);
}